// round 5
// baseline (speedup 1.0000x reference)
#include <cuda_runtime.h>

#define B_  128
#define T_  64
#define N_  81
#define M_  128
#define G4_ 512

// scratch (static device globals — no allocs)
__device__ float g_hc[B_ * T_ * 2 * M_];   // [h;c]                  (128,64,256)
__device__ float g_alpha[B_ * T_ * N_];    // softmax(scores)        (128,64,81)

typedef unsigned long long ull;

__device__ __forceinline__ float frcp(float x) {
    float r; asm("rcp.approx.ftz.f32 %0, %1;" : "=f"(r) : "f"(x)); return r;
}
__device__ __forceinline__ float sigm(float x) {
    return frcp(1.0f + __expf(-x));
}
__device__ __forceinline__ float tanhe(float x) {           // exp-based, accurate
    return 2.0f * frcp(1.0f + __expf(-2.0f * x)) - 1.0f;
}
__device__ __forceinline__ float tanhap(float x) {          // HW tanh, 1 MUFU
    float r; asm("tanh.approx.f32 %0, %1;" : "=f"(r) : "f"(x)); return r;
}
__device__ __forceinline__ ull pk2(float a, float b) {
    ull r; asm("mov.b64 %0, {%1, %2};" : "=l"(r) : "f"(a), "f"(b)); return r;
}
__device__ __forceinline__ ull fma2(ull a, ull b, ull c) {
    ull d;
    asm("fma.rn.f32x2 %0, %1, %2, %3;" : "=l"(d) : "l"(a), "l"(b), "l"(c));
    return d;
}
__device__ __forceinline__ void unpk2(ull v, float& lo, float& hi) {
    asm("mov.b64 {%0, %1}, %2;" : "=f"(lo), "=f"(hi) : "l"(v));
}

// ---------------------------------------------------------------------------
// K1: z = h0@U_lstm + b (inline) ; gates = X@W_lstm + z ; LSTM cell ; hc=[h;c]
// grid = B, 512 threads = 16 warps; warp = (t-group of 8) x (m 32-band),
// 2 stages over m-halves. Inner math packed f32x2 over t-pairs.
// ---------------------------------------------------------------------------
#define GATES_SMEM ((81 * 66 + 81 * 256) * 4)
__global__ void __launch_bounds__(512, 1)
k_gates(const float* __restrict__ X,
        const float* __restrict__ Wl,
        const float* __restrict__ s0,
        const float* __restrict__ h0,
        const float* __restrict__ Ul,
        const float* __restrict__ bl) {
    extern __shared__ float sm[];
    float* Xst = sm;              // [k][t] transposed, pitch 66
    float* Ws  = sm + 81 * 66;    // [k][gate][c64]  (one m-half)
    __shared__ float hs[M_];
    __shared__ float zsm[G4_];
    int b = blockIdx.x;
    int tid = threadIdx.x;
    int wid = tid >> 5, lane = tid & 31;
    int wrow = (wid & 7) * 8;     // 8 t-rows per warp
    int ml = wid >> 3;            // 32-col band within the 64-col half

    for (int idx = tid; idx < T_ * N_; idx += 512) {
        int t = idx / N_, k = idx - t * N_;
        Xst[k * 66 + t] = X[b * T_ * N_ + idx];
    }
    if (tid < M_) hs[tid] = h0[b * M_ + tid];
    __syncthreads();
    // z[g] for this b
    {
        float acc = bl[tid];
#pragma unroll 8
        for (int k = 0; k < M_; k++) acc += hs[k] * Ul[k * G4_ + tid];
        zsm[tid] = acc;
    }

    for (int stage = 0; stage < 2; stage++) {
        __syncthreads();
        for (int idx = tid; idx < 81 * 256; idx += 512) {
            int k = idx >> 8, j = idx & 255;
            int g = j >> 6, c = j & 63;
            Ws[idx] = Wl[k * G4_ + g * M_ + stage * 64 + c];
        }
        __syncthreads();

        ull acc[4][4];
#pragma unroll
        for (int g = 0; g < 4; g++)
#pragma unroll
            for (int p = 0; p < 4; p++) acc[g][p] = 0ull;

#pragma unroll 3
        for (int k = 0; k < 81; k++) {
            const float* xr = &Xst[k * 66 + wrow];
            ull x0 = *(const ull*)(xr + 0);
            ull x1 = *(const ull*)(xr + 2);
            ull x2 = *(const ull*)(xr + 4);
            ull x3 = *(const ull*)(xr + 6);
            int wk = k * 256 + ml * 32 + lane;
            float wi = Ws[wk +   0];
            float wf = Ws[wk +  64];
            float wg = Ws[wk + 128];
            float wo = Ws[wk + 192];
            ull di = pk2(wi, wi);
            ull df = pk2(wf, wf);
            ull dg = pk2(wg, wg);
            ull do_ = pk2(wo, wo);
            acc[0][0] = fma2(x0, di, acc[0][0]);
            acc[0][1] = fma2(x1, di, acc[0][1]);
            acc[0][2] = fma2(x2, di, acc[0][2]);
            acc[0][3] = fma2(x3, di, acc[0][3]);
            acc[1][0] = fma2(x0, df, acc[1][0]);
            acc[1][1] = fma2(x1, df, acc[1][1]);
            acc[1][2] = fma2(x2, df, acc[1][2]);
            acc[1][3] = fma2(x3, df, acc[1][3]);
            acc[2][0] = fma2(x0, dg, acc[2][0]);
            acc[2][1] = fma2(x1, dg, acc[2][1]);
            acc[2][2] = fma2(x2, dg, acc[2][2]);
            acc[2][3] = fma2(x3, dg, acc[2][3]);
            acc[3][0] = fma2(x0, do_, acc[3][0]);
            acc[3][1] = fma2(x1, do_, acc[3][1]);
            acc[3][2] = fma2(x2, do_, acc[3][2]);
            acc[3][3] = fma2(x3, do_, acc[3][3]);
        }

        int m = stage * 64 + ml * 32 + lane;
        float zi = zsm[0 * M_ + m];
        float zf = zsm[1 * M_ + m];
        float zg = zsm[2 * M_ + m];
        float zo = zsm[3 * M_ + m];
        float sv = s0[b * M_ + m];
#pragma unroll
        for (int p = 0; p < 4; p++) {
            float vi[2], vf[2], vg[2], vo[2];
            unpk2(acc[0][p], vi[0], vi[1]);
            unpk2(acc[1][p], vf[0], vf[1]);
            unpk2(acc[2][p], vg[0], vg[1]);
            unpk2(acc[3][p], vo[0], vo[1]);
#pragma unroll
            for (int h = 0; h < 2; h++) {
                int t = wrow + 2 * p + h;
                float iv = sigm(vi[h] + zi);
                float fv = sigm(vf[h] + zf);
                float gv = tanhe(vg[h] + zg);
                float ov = sigm(vo[h] + zo);
                float cc = fv * sv + iv * gv;
                float hh = ov * tanhe(cc);
                g_hc[(b * T_ + t) * 256 + m]       = hh;
                g_hc[(b * T_ + t) * 256 + M_ + m]  = cc;
            }
        }
    }
}

// ---------------------------------------------------------------------------
// K2 (fused): per b —
//   A[t,j]  = hc[t,:] @ We_w[:,j] + We_b[j]   (64x64, K=256)  [f32x2 t-pairs]
//   U[i,k]  = sum_t X[b,t,i]*Ue_w[t,k] + Ue_b[k]
//   scores[t,i] = sum_k v[k]*tanh(A[t,k]+U[i,k]); alpha = softmax_i
// ---------------------------------------------------------------------------
#define AS_OFF  0
#define US_OFF  (64 * 65)                  // 4160
#define US_PAD  (96 * 65)                  // padded rows: lane+64 reads stay in-region
#define SC_OFF  (US_OFF + US_PAD)          // 10400  scratch (12416 floats)
#define SC_SZ   (64 * 66 + 64 * 64 * 2)    // hcsT + Wes2(dup)
#define VS_OFF  (SC_OFF + SC_SZ)
#define UB_OFF  (VS_OFF + 64)
#define ATTN_SMEM ((UB_OFF + 64) * 4)
__global__ void __launch_bounds__(512, 1)
k_attn(const float* __restrict__ Wew, const float* __restrict__ Web,
       const float* __restrict__ X,   const float* __restrict__ Uew,
       const float* __restrict__ Ueb, const float* __restrict__ vew) {
    extern __shared__ float sm[];
    float* As = sm + AS_OFF;    // [t][k] pitch 65
    float* Us = sm + US_OFF;    // [i][k] pitch 65 (rows padded to 96)
    float* S  = sm + SC_OFF;    // scratch
    float* vs = sm + VS_OFF;
    float* ub = sm + UB_OFF;
    int b = blockIdx.x, tid = threadIdx.x;

    // ---- phase 1: A = hc @ We_w + We_b  (f32x2 over t-pairs) ----
    {
        float* hcsT  = S;               // [k][t] pitch 66 (t-pairs 8B aligned)
        float* Wes2f = S + 64 * 66;     // [k][c] duplicated (w,w) pairs: 64*128
        int rowg = tid >> 4;            // 32 groups of 2 t
        int c0   = (tid & 15) * 4;      // 4 cols
        ull acc[4];
#pragma unroll
        for (int j = 0; j < 4; j++) {
            float wb = Web[c0 + j];
            acc[j] = pk2(wb, wb);
        }

        for (int kc = 0; kc < 4; kc++) {
            __syncthreads();
            for (int idx = tid; idx < 4096; idx += 512) {
                int t = idx >> 6, kk = idx & 63;
                hcsT[kk * 66 + t] = g_hc[(b * T_ + t) * 256 + kc * 64 + kk];
            }
            for (int idx = tid; idx < 4096; idx += 512) {
                int kk = idx >> 6, c = idx & 63;
                float w = Wew[kc * 4096 + idx];
                ((float2*)Wes2f)[kk * 64 + c] = make_float2(w, w);
            }
            __syncthreads();
#pragma unroll 4
            for (int k = 0; k < 64; k++) {
                ull x2 = *(const ull*)&hcsT[k * 66 + rowg * 2];
                ulonglong2 wa = *(const ulonglong2*)&Wes2f[k * 128 + c0 * 2];
                ulonglong2 wb2 = *(const ulonglong2*)&Wes2f[k * 128 + c0 * 2 + 4];
                acc[0] = fma2(x2, wa.x, acc[0]);
                acc[1] = fma2(x2, wa.y, acc[1]);
                acc[2] = fma2(x2, wb2.x, acc[2]);
                acc[3] = fma2(x2, wb2.y, acc[3]);
            }
        }
#pragma unroll
        for (int j = 0; j < 4; j++) {
            float lo, hi;
            unpk2(acc[j], lo, hi);
            As[(rowg * 2 + 0) * 65 + c0 + j] = lo;
            As[(rowg * 2 + 1) * 65 + c0 + j] = hi;
        }
    }

    // ---- phase 2: U ----
    __syncthreads();
    {
        float* Xs  = S;            // 5184
        float* Ues = S + 5184;     // 4096
        for (int idx = tid; idx < 5184; idx += 512) Xs[idx] = X[b * 5184 + idx];
        for (int idx = tid; idx < 4096; idx += 512) Ues[idx] = Uew[idx];
        if (tid < 64)                vs[tid]       = vew[tid];
        else if (tid < 128)          ub[tid - 64]  = Ueb[tid - 64];
        __syncthreads();

        if (tid < 336) {
            int ig = tid >> 4, kq = tid & 15, i0 = ig * 4;
            int ni = (i0 + 4 <= N_) ? 4 : (N_ - i0);
            float4 bias = *(const float4*)&ub[kq * 4];
            float4 a0 = bias, a1 = bias, a2 = bias, a3 = bias;
#pragma unroll 4
            for (int t = 0; t < T_; t++) {
                float4 u = *(const float4*)&Ues[t * 64 + kq * 4];
                const float* xr = &Xs[t * N_ + i0];
                float x0 = xr[0], x1 = xr[1], x2 = xr[2], x3 = xr[3];
                a0.x += x0 * u.x; a0.y += x0 * u.y; a0.z += x0 * u.z; a0.w += x0 * u.w;
                a1.x += x1 * u.x; a1.y += x1 * u.y; a1.z += x1 * u.z; a1.w += x1 * u.w;
                a2.x += x2 * u.x; a2.y += x2 * u.y; a2.z += x2 * u.z; a2.w += x2 * u.w;
                a3.x += x3 * u.x; a3.y += x3 * u.y; a3.z += x3 * u.z; a3.w += x3 * u.w;
            }
            float4 av[4] = {a0, a1, a2, a3};
            for (int j = 0; j < ni; j++) {
                float* up = &Us[(i0 + j) * 65 + kq * 4];
                up[0] = av[j].x; up[1] = av[j].y; up[2] = av[j].z; up[3] = av[j].w;
            }
        }
    }

    // ---- phase 3: scores + softmax + alpha ----
    __syncthreads();
    {
        int wid = tid >> 5, lane = tid & 31;
        bool v2 = (lane + 64 < N_);
        for (int t = wid; t < T_; t += 16) {
            float a0 = 0.f, a1 = 0.f, a2 = 0.f;
            const float* Ap = &As[t * 65];
            const float* U0 = &Us[lane * 65];
            const float* U1 = &Us[(lane + 32) * 65];
            const float* U2 = &Us[(lane + 64) * 65];  // padded region: safe read
#pragma unroll 4
            for (int k = 0; k < 64; k++) {
                float av = Ap[k], vv = vs[k];
                a0 += vv * tanhap(av + U0[k]);
                a1 += vv * tanhap(av + U1[k]);
                a2 += vv * tanhap(av + U2[k]);
            }
            if (!v2) a2 = -1e30f;
            float mx = fmaxf(fmaxf(a0, a1), a2);
#pragma unroll
            for (int off = 16; off; off >>= 1)
                mx = fmaxf(mx, __shfl_xor_sync(0xffffffffu, mx, off));
            float e0 = __expf(a0 - mx);
            float e1 = __expf(a1 - mx);
            float e2 = __expf(a2 - mx);   // 0 when invalid (a2=-1e30)
            float sum = e0 + e1 + e2;
#pragma unroll
            for (int off = 16; off; off >>= 1)
                sum += __shfl_xor_sync(0xffffffffu, sum, off);
            float inv = frcp(sum);
            float* ap = &g_alpha[b * (T_ * N_) + t * N_];
            ap[lane]      = e0 * inv;
            ap[lane + 32] = e1 * inv;
            if (v2) ap[lane + 64] = e2 * inv;
        }
    }
}

// ---------------------------------------------------------------------------
// K3: out[t,b,tp,i] = X[b,tp,i] * alpha[b,t,i]
// Since gcd(4,81)=1, the float4->i mapping has period 81 in float4 index.
// Per t: expanded LUT alxp[81] of float4; X cached in registers.
// grid = B*4 (16 t each), 512 threads.
// ---------------------------------------------------------------------------
__global__ void __launch_bounds__(512, 1)
k_out(const float* __restrict__ X, float* __restrict__ out) {
    __shared__ float4 alxp[16][N_];    // 20736 B
    int b = blockIdx.x >> 2, tg = blockIdx.x & 3;
    int tid = threadIdx.x;

    // build expanded alpha LUTs for the 16 t's
    for (int idx = tid; idx < 16 * N_; idx += 512) {
        int tt = idx / N_, r = idx - tt * N_;
        const float* al = &g_alpha[b * (T_ * N_) + (tg * 16 + tt) * N_];
        int i0 = (4 * r) % N_;
        int i1 = i0 + 1; if (i1 >= N_) i1 -= N_;
        int i2 = i1 + 1; if (i2 >= N_) i2 -= N_;
        int i3 = i2 + 1; if (i3 >= N_) i3 -= N_;
        alxp[tt][r] = make_float4(al[i0], al[i1], al[i2], al[i3]);
    }

    // X rows of this b into registers (3 float4 slots per thread)
    const float4* X4 = (const float4*)(X + b * (T_ * N_));
    int j0 = tid, j1 = tid + 512, j2 = tid + 1024;
    bool has2 = (j2 < 1296);
    float4 x0 = X4[j0];
    float4 x1 = X4[j1];
    float4 x2 = has2 ? X4[j2] : make_float4(0, 0, 0, 0);
    int r0 = j0 % N_, r1 = j1 % N_, r2 = j2 % N_;
    __syncthreads();

    float4* out4 = (float4*)out;
#pragma unroll 4
    for (int tt = 0; tt < 16; tt++) {
        float4* O = out4 + (size_t)((tg * 16 + tt) * B_ + b) * 1296;
        float4 a0 = alxp[tt][r0];
        float4 o0 = make_float4(x0.x * a0.x, x0.y * a0.y, x0.z * a0.z, x0.w * a0.w);
        O[j0] = o0;
        float4 a1 = alxp[tt][r1];
        float4 o1 = make_float4(x1.x * a1.x, x1.y * a1.y, x1.z * a1.z, x1.w * a1.w);
        O[j1] = o1;
        if (has2) {
            float4 a2 = alxp[tt][r2];
            float4 o2 = make_float4(x2.x * a2.x, x2.y * a2.y, x2.z * a2.z, x2.w * a2.w);
            O[j2] = o2;
        }
    }
}

// ---------------------------------------------------------------------------
extern "C" void kernel_launch(void* const* d_in, const int* in_sizes, int n_in,
                              void* d_out, int out_size) {
    const float* X   = (const float*)d_in[0];
    const float* h0  = (const float*)d_in[1];
    const float* s0  = (const float*)d_in[2];
    const float* Wl  = (const float*)d_in[3];
    const float* Ul  = (const float*)d_in[4];
    const float* bl  = (const float*)d_in[5];
    const float* Wew = (const float*)d_in[6];
    const float* Web = (const float*)d_in[7];
    const float* Uew = (const float*)d_in[8];
    const float* Ueb = (const float*)d_in[9];
    const float* vew = (const float*)d_in[10];
    // d_in[11] = ve_b: constant pre-softmax shift -> softmax-invariant, unused.
    float* out = (float*)d_out;

    cudaFuncSetAttribute(k_gates, cudaFuncAttributeMaxDynamicSharedMemorySize, GATES_SMEM);
    cudaFuncSetAttribute(k_attn,  cudaFuncAttributeMaxDynamicSharedMemorySize, ATTN_SMEM);

    k_gates<<<B_,     512, GATES_SMEM>>>(X, Wl, s0, h0, Ul, bl);
    k_attn <<<B_,     512, ATTN_SMEM>>>(Wew, Web, X, Uew, Ueb, vew);
    k_out  <<<B_ * 4, 512>>>(X, out);
    (void)in_sizes; (void)n_in; (void)out_size;
}

// round 6
// speedup vs baseline: 1.2739x; 1.2739x over previous
#include <cuda_runtime.h>

#define B_  128
#define T_  64
#define N_  81
#define M_  128
#define G4_ 512

// scratch (static device globals — no allocs)
__device__ float g_z[B_ * G4_];            // h0@U_lstm + b_lstm     (128,512)
__device__ float g_hc[B_ * T_ * 2 * M_];   // [h;c]                  (128,64,256)
__device__ float g_alpha[B_ * T_ * N_];    // softmax(scores)        (128,64,81)

typedef unsigned long long ull;

__device__ __forceinline__ float frcp(float x) {
    float r; asm("rcp.approx.ftz.f32 %0, %1;" : "=f"(r) : "f"(x)); return r;
}
__device__ __forceinline__ float sigm(float x) {
    return frcp(1.0f + __expf(-x));
}
__device__ __forceinline__ float tanhe(float x) {           // exp-based, accurate
    return 2.0f * frcp(1.0f + __expf(-2.0f * x)) - 1.0f;
}
__device__ __forceinline__ float tanhap(float x) {          // HW tanh, 1 MUFU
    float r; asm("tanh.approx.f32 %0, %1;" : "=f"(r) : "f"(x)); return r;
}
__device__ __forceinline__ ull pk2(float a, float b) {
    ull r; asm("mov.b64 %0, {%1, %2};" : "=l"(r) : "f"(a), "f"(b)); return r;
}
__device__ __forceinline__ ull fma2(ull a, ull b, ull c) {
    ull d;
    asm("fma.rn.f32x2 %0, %1, %2, %3;" : "=l"(d) : "l"(a), "l"(b), "l"(c));
    return d;
}
__device__ __forceinline__ void unpk2(ull v, float& lo, float& hi) {
    asm("mov.b64 {%0, %1}, %2;" : "=f"(lo), "=f"(hi) : "l"(v));
}

// ---------------------------------------------------------------------------
// K0: z[b,g] = b_lstm[g] + sum_k h0[b,k] * U_lstm[k,g]
// ---------------------------------------------------------------------------
__global__ void k_z(const float* __restrict__ h0,
                    const float* __restrict__ Ul,
                    const float* __restrict__ bl) {
    __shared__ float hs[M_];
    int b = blockIdx.x, g = threadIdx.x;           // 512 threads
    if (g < M_) hs[g] = h0[b * M_ + g];
    __syncthreads();
    float acc = bl[g];
#pragma unroll 8
    for (int k = 0; k < M_; k++) acc += hs[k] * Ul[k * G4_ + g];
    g_z[b * G4_ + g] = acc;
}

// ---------------------------------------------------------------------------
// K1: gates = X@W_lstm + z ; LSTM cell ; hc=[h;c]
// grid = B*2 (32 t per block), 512 threads = 16 warps, 2 blocks/SM.
// warp = (t-group of 4) x (m 32-band); 2 stages over m-halves.
// Packed f32x2 over t-pairs. smem: Xst 81*34 + Ws 81*256 floats (~94KB).
// ---------------------------------------------------------------------------
#define GATES_SMEM ((81 * 34 + 81 * 256) * 4)
__global__ void __launch_bounds__(512, 2)
k_gates(const float* __restrict__ X,
        const float* __restrict__ Wl,
        const float* __restrict__ s0) {
    extern __shared__ float sm[];
    float* Xst = sm;              // [k][t] transposed, pitch 34 (32 t rows)
    float* Ws  = sm + 81 * 34;    // [k][gate][c64]  (one m-half)
    int b = blockIdx.x >> 1, th = blockIdx.x & 1;
    int t0 = th * 32;
    int tid = threadIdx.x;
    int wid = tid >> 5, lane = tid & 31;
    int wrow = (wid & 7) * 4;     // 4 t-rows per warp (within the 32)
    int ml = wid >> 3;            // 32-col band within the 64-col half

    for (int idx = tid; idx < 32 * 81; idx += 512) {
        int t = idx / 81, k = idx - t * 81;
        Xst[k * 34 + t] = X[(b * T_ + t0 + t) * N_ + k];
    }

    for (int stage = 0; stage < 2; stage++) {
        __syncthreads();
        for (int idx = tid; idx < 81 * 256; idx += 512) {
            int k = idx >> 8, j = idx & 255;
            int g = j >> 6, c = j & 63;
            Ws[idx] = Wl[k * G4_ + g * M_ + stage * 64 + c];
        }
        __syncthreads();

        ull acc[4][2];
#pragma unroll
        for (int g = 0; g < 4; g++)
#pragma unroll
            for (int p = 0; p < 2; p++) acc[g][p] = 0ull;

#pragma unroll 3
        for (int k = 0; k < 81; k++) {
            const float* xr = &Xst[k * 34 + wrow];
            ull x0 = *(const ull*)(xr + 0);
            ull x1 = *(const ull*)(xr + 2);
            int wk = k * 256 + ml * 32 + lane;
            float wi = Ws[wk +   0];
            float wf = Ws[wk +  64];
            float wg = Ws[wk + 128];
            float wo = Ws[wk + 192];
            ull di = pk2(wi, wi);
            ull df = pk2(wf, wf);
            ull dg = pk2(wg, wg);
            ull do_ = pk2(wo, wo);
            acc[0][0] = fma2(x0, di, acc[0][0]);
            acc[0][1] = fma2(x1, di, acc[0][1]);
            acc[1][0] = fma2(x0, df, acc[1][0]);
            acc[1][1] = fma2(x1, df, acc[1][1]);
            acc[2][0] = fma2(x0, dg, acc[2][0]);
            acc[2][1] = fma2(x1, dg, acc[2][1]);
            acc[3][0] = fma2(x0, do_, acc[3][0]);
            acc[3][1] = fma2(x1, do_, acc[3][1]);
        }

        int m = stage * 64 + ml * 32 + lane;
        float zi = g_z[b * G4_ + 0 * M_ + m];
        float zf = g_z[b * G4_ + 1 * M_ + m];
        float zg = g_z[b * G4_ + 2 * M_ + m];
        float zo = g_z[b * G4_ + 3 * M_ + m];
        float sv = s0[b * M_ + m];
#pragma unroll
        for (int p = 0; p < 2; p++) {
            float vi[2], vf[2], vg[2], vo[2];
            unpk2(acc[0][p], vi[0], vi[1]);
            unpk2(acc[1][p], vf[0], vf[1]);
            unpk2(acc[2][p], vg[0], vg[1]);
            unpk2(acc[3][p], vo[0], vo[1]);
#pragma unroll
            for (int h = 0; h < 2; h++) {
                int t = t0 + wrow + 2 * p + h;
                float iv = sigm(vi[h] + zi);
                float fv = sigm(vf[h] + zf);
                float gv = tanhe(vg[h] + zg);
                float ov = sigm(vo[h] + zo);
                float cc = fv * sv + iv * gv;
                float hh = ov * tanhe(cc);
                g_hc[(b * T_ + t) * 256 + m]       = hh;
                g_hc[(b * T_ + t) * 256 + M_ + m]  = cc;
            }
        }
    }
}

// ---------------------------------------------------------------------------
// K2 (fused): per b —
//   A[t,j]  = hc[t,:] @ We_w[:,j] + We_b[j]             (64x64, K=256)
//   U[i,k]  = sum_t X[b,t,i]*Ue_w[t,k] + Ue_b[k]        (81x64)
//   scores[t,i] = sum_k v[k]*tanh(A[t,k]+U[i,k]); alpha = softmax_i
// grid = B, 512 threads.
// ---------------------------------------------------------------------------
#define AS_OFF  0
#define US_OFF  (64 * 65)                  // 4160
#define US_PAD  (96 * 65)                  // padded rows: lane+64 reads stay in-region
#define SC_OFF  (US_OFF + US_PAD)          // 10400  scratch (9280 floats)
#define VS_OFF  (SC_OFF + 9280)            // 19680
#define UB_OFF  (VS_OFF + 64)              // 19744
#define ATTN_SMEM ((UB_OFF + 64) * 4)      // 79232 B
__global__ void __launch_bounds__(512, 1)
k_attn(const float* __restrict__ Wew, const float* __restrict__ Web,
       const float* __restrict__ X,   const float* __restrict__ Uew,
       const float* __restrict__ Ueb, const float* __restrict__ vew) {
    extern __shared__ float sm[];
    float* As = sm + AS_OFF;    // [t][k] pitch 65
    float* Us = sm + US_OFF;    // [i][k] pitch 65 (rows padded to 96)
    float* S  = sm + SC_OFF;    // scratch
    float* vs = sm + VS_OFF;
    float* ub = sm + UB_OFF;
    int b = blockIdx.x, tid = threadIdx.x;

    // ---- phase 1: A = hc @ We_w + We_b (scalar, broadcast-friendly) ----
    {
        float* hcs = S;            // 64*65
        float* Wes = S + 64 * 65;  // 64*64
        int r0 = (tid >> 4) * 2;
        int c0 = (tid & 15) * 4;
        float acc[2][4];
#pragma unroll
        for (int i = 0; i < 2; i++)
#pragma unroll
            for (int j = 0; j < 4; j++) acc[i][j] = Web[c0 + j];

        for (int kc = 0; kc < 4; kc++) {
            __syncthreads();
            for (int idx = tid; idx < 4096; idx += 512) {
                int t = idx >> 6, kk = idx & 63;
                hcs[t * 65 + kk] = g_hc[(b * T_ + t) * 256 + kc * 64 + kk];
            }
            for (int idx = tid; idx < 4096; idx += 512)
                Wes[idx] = Wew[kc * 4096 + idx];
            __syncthreads();
#pragma unroll 4
            for (int k = 0; k < 64; k++) {
                float a0 = hcs[r0 * 65 + k];
                float a1 = hcs[(r0 + 1) * 65 + k];
                float4 w = *(const float4*)&Wes[k * 64 + c0];
                acc[0][0] += a0 * w.x; acc[0][1] += a0 * w.y;
                acc[0][2] += a0 * w.z; acc[0][3] += a0 * w.w;
                acc[1][0] += a1 * w.x; acc[1][1] += a1 * w.y;
                acc[1][2] += a1 * w.z; acc[1][3] += a1 * w.w;
            }
        }
#pragma unroll
        for (int i = 0; i < 2; i++)
#pragma unroll
            for (int j = 0; j < 4; j++)
                As[(r0 + i) * 65 + c0 + j] = acc[i][j];
    }

    // ---- phase 2: U ----
    __syncthreads();
    {
        float* Xs  = S;            // 5184
        float* Ues = S + 5184;     // 4096
        for (int idx = tid; idx < 5184; idx += 512) Xs[idx] = X[b * 5184 + idx];
        for (int idx = tid; idx < 4096; idx += 512) Ues[idx] = Uew[idx];
        if (tid < 64)                vs[tid]       = vew[tid];
        else if (tid < 128)          ub[tid - 64]  = Ueb[tid - 64];
        __syncthreads();

        if (tid < 336) {
            int ig = tid >> 4, kq = tid & 15, i0 = ig * 4;
            int ni = (i0 + 4 <= N_) ? 4 : (N_ - i0);
            float4 bias = *(const float4*)&ub[kq * 4];
            float4 a0 = bias, a1 = bias, a2 = bias, a3 = bias;
#pragma unroll 4
            for (int t = 0; t < T_; t++) {
                float4 u = *(const float4*)&Ues[t * 64 + kq * 4];
                const float* xr = &Xs[t * N_ + i0];
                float x0 = xr[0], x1 = xr[1], x2 = xr[2], x3 = xr[3];
                a0.x += x0 * u.x; a0.y += x0 * u.y; a0.z += x0 * u.z; a0.w += x0 * u.w;
                a1.x += x1 * u.x; a1.y += x1 * u.y; a1.z += x1 * u.z; a1.w += x1 * u.w;
                a2.x += x2 * u.x; a2.y += x2 * u.y; a2.z += x2 * u.z; a2.w += x2 * u.w;
                a3.x += x3 * u.x; a3.y += x3 * u.y; a3.z += x3 * u.z; a3.w += x3 * u.w;
            }
            float4 av[4] = {a0, a1, a2, a3};
            for (int j = 0; j < ni; j++) {
                float* up = &Us[(i0 + j) * 65 + kq * 4];
                up[0] = av[j].x; up[1] = av[j].y; up[2] = av[j].z; up[3] = av[j].w;
            }
        }
    }

    // ---- phase 3: scores + softmax + alpha ----
    __syncthreads();
    {
        int wid = tid >> 5, lane = tid & 31;
        bool v2 = (lane + 64 < N_);
        for (int t = wid; t < T_; t += 16) {
            float a0 = 0.f, a1 = 0.f, a2 = 0.f;
            const float* Ap = &As[t * 65];
            const float* U0 = &Us[lane * 65];
            const float* U1 = &Us[(lane + 32) * 65];
            const float* U2 = &Us[(lane + 64) * 65];  // padded region: safe read
#pragma unroll 4
            for (int k = 0; k < 64; k++) {
                float av = Ap[k], vv = vs[k];
                a0 += vv * tanhap(av + U0[k]);
                a1 += vv * tanhap(av + U1[k]);
                a2 += vv * tanhap(av + U2[k]);
            }
            if (!v2) a2 = -1e30f;
            float mx = fmaxf(fmaxf(a0, a1), a2);
#pragma unroll
            for (int off = 16; off; off >>= 1)
                mx = fmaxf(mx, __shfl_xor_sync(0xffffffffu, mx, off));
            float e0 = __expf(a0 - mx);
            float e1 = __expf(a1 - mx);
            float e2 = __expf(a2 - mx);   // 0 when invalid (a2=-1e30)
            float sum = e0 + e1 + e2;
#pragma unroll
            for (int off = 16; off; off >>= 1)
                sum += __shfl_xor_sync(0xffffffffu, sum, off);
            float inv = frcp(sum);
            float* ap = &g_alpha[b * (T_ * N_) + t * N_];
            ap[lane]      = e0 * inv;
            ap[lane + 32] = e1 * inv;
            if (v2) ap[lane + 64] = e2 * inv;
        }
    }
}

// ---------------------------------------------------------------------------
// K3: out[t,b,tp,i] = X[b,tp,i] * alpha[b,t,i]
// gcd(4,81)=1 -> float4->i mapping has period 81; per-t expanded float4 LUT,
// X cached in registers. grid = B*4 (16 t each), 512 threads.
// ---------------------------------------------------------------------------
__global__ void __launch_bounds__(512, 2)
k_out(const float* __restrict__ X, float* __restrict__ out) {
    __shared__ float4 alxp[16][N_];    // 20736 B
    int b = blockIdx.x >> 2, tg = blockIdx.x & 3;
    int tid = threadIdx.x;

    // build expanded alpha LUTs for the 16 t's
    for (int idx = tid; idx < 16 * N_; idx += 512) {
        int tt = idx / N_, r = idx - tt * N_;
        const float* al = &g_alpha[b * (T_ * N_) + (tg * 16 + tt) * N_];
        int i0 = (4 * r) % N_;
        int i1 = i0 + 1; if (i1 >= N_) i1 -= N_;
        int i2 = i1 + 1; if (i2 >= N_) i2 -= N_;
        int i3 = i2 + 1; if (i3 >= N_) i3 -= N_;
        alxp[tt][r] = make_float4(al[i0], al[i1], al[i2], al[i3]);
    }

    // X rows of this b into registers (3 float4 slots per thread)
    const float4* X4 = (const float4*)(X + b * (T_ * N_));
    int j0 = tid, j1 = tid + 512, j2 = tid + 1024;
    bool has2 = (j2 < 1296);
    float4 x0 = X4[j0];
    float4 x1 = X4[j1];
    float4 x2 = has2 ? X4[j2] : make_float4(0, 0, 0, 0);
    int r0 = j0 % N_, r1 = j1 % N_, r2 = j2 % N_;
    __syncthreads();

    float4* out4 = (float4*)out;
#pragma unroll 4
    for (int tt = 0; tt < 16; tt++) {
        float4* O = out4 + (size_t)((tg * 16 + tt) * B_ + b) * 1296;
        float4 a0 = alxp[tt][r0];
        float4 o0 = make_float4(x0.x * a0.x, x0.y * a0.y, x0.z * a0.z, x0.w * a0.w);
        O[j0] = o0;
        float4 a1 = alxp[tt][r1];
        float4 o1 = make_float4(x1.x * a1.x, x1.y * a1.y, x1.z * a1.z, x1.w * a1.w);
        O[j1] = o1;
        if (has2) {
            float4 a2 = alxp[tt][r2];
            float4 o2 = make_float4(x2.x * a2.x, x2.y * a2.y, x2.z * a2.z, x2.w * a2.w);
            O[j2] = o2;
        }
    }
}

// ---------------------------------------------------------------------------
extern "C" void kernel_launch(void* const* d_in, const int* in_sizes, int n_in,
                              void* d_out, int out_size) {
    const float* X   = (const float*)d_in[0];
    const float* h0  = (const float*)d_in[1];
    const float* s0  = (const float*)d_in[2];
    const float* Wl  = (const float*)d_in[3];
    const float* Ul  = (const float*)d_in[4];
    const float* bl  = (const float*)d_in[5];
    const float* Wew = (const float*)d_in[6];
    const float* Web = (const float*)d_in[7];
    const float* Uew = (const float*)d_in[8];
    const float* Ueb = (const float*)d_in[9];
    const float* vew = (const float*)d_in[10];
    // d_in[11] = ve_b: constant pre-softmax shift -> softmax-invariant, unused.
    float* out = (float*)d_out;

    cudaFuncSetAttribute(k_gates, cudaFuncAttributeMaxDynamicSharedMemorySize, GATES_SMEM);
    cudaFuncSetAttribute(k_attn,  cudaFuncAttributeMaxDynamicSharedMemorySize, ATTN_SMEM);

    k_z    <<<B_,     G4_>>>(h0, Ul, bl);
    k_gates<<<B_ * 2, 512, GATES_SMEM>>>(X, Wl, s0);
    k_attn <<<B_,     512, ATTN_SMEM>>>(Wew, Web, X, Uew, Ueb, vew);
    k_out  <<<B_ * 4, 512>>>(X, out);
    (void)in_sizes; (void)n_in; (void)out_size;
}

// round 8
// speedup vs baseline: 1.4393x; 1.1298x over previous
#include <cuda_runtime.h>

#define B_  128
#define T_  64
#define N_  81
#define M_  128
#define G4_ 512

// scratch (static device globals — no allocs)
__device__ float g_z[B_ * G4_];            // h0@U_lstm + b_lstm     (128,512)
__device__ float g_hc[B_ * T_ * 2 * M_];   // [h;c]                  (128,64,256)

typedef unsigned long long ull;

__device__ __forceinline__ float frcp(float x) {
    float r; asm("rcp.approx.ftz.f32 %0, %1;" : "=f"(r) : "f"(x)); return r;
}
__device__ __forceinline__ float sigm(float x) {
    return frcp(1.0f + __expf(-x));
}
__device__ __forceinline__ float tanhe(float x) {           // exp-based, accurate
    return 2.0f * frcp(1.0f + __expf(-2.0f * x)) - 1.0f;
}
__device__ __forceinline__ float tanhap(float x) {          // HW tanh, 1 MUFU
    float r; asm("tanh.approx.f32 %0, %1;" : "=f"(r) : "f"(x)); return r;
}
__device__ __forceinline__ ull pk2(float a, float b) {
    ull r; asm("mov.b64 %0, {%1, %2};" : "=l"(r) : "f"(a), "f"(b)); return r;
}
__device__ __forceinline__ ull fma2(ull a, ull b, ull c) {
    ull d;
    asm("fma.rn.f32x2 %0, %1, %2, %3;" : "=l"(d) : "l"(a), "l"(b), "l"(c));
    return d;
}
__device__ __forceinline__ void unpk2(ull v, float& lo, float& hi) {
    asm("mov.b64 {%0, %1}, %2;" : "=f"(lo), "=f"(hi) : "l"(v));
}

// ---------------------------------------------------------------------------
// K0: z[b,g] = b_lstm[g] + sum_k h0[b,k] * U_lstm[k,g]
// ---------------------------------------------------------------------------
__global__ void k_z(const float* __restrict__ h0,
                    const float* __restrict__ Ul,
                    const float* __restrict__ bl) {
    __shared__ float hs[M_];
    int b = blockIdx.x, g = threadIdx.x;           // 512 threads
    if (g < M_) hs[g] = h0[b * M_ + g];
    __syncthreads();
    float acc = bl[g];
#pragma unroll 8
    for (int k = 0; k < M_; k++) acc += hs[k] * Ul[k * G4_ + g];
    g_z[b * G4_ + g] = acc;
}

// ---------------------------------------------------------------------------
// K1: gates = X@W_lstm + z ; LSTM cell ; hc=[h;c]
// grid = B*2 (32 t per block), 512 threads = 16 warps, 2 blocks/SM.
// warp = (t-group of 4) x (m 32-band); 2 stages over m-halves.
// Ws laid out [k][c][gate] so one LDS.128 fetches all 4 gate weights.
// ---------------------------------------------------------------------------
#define XST_PITCH 34
#define WS_OFF    2756                          // 16B-aligned (2756*4 % 16 == 0)
#define GATES_SMEM ((WS_OFF + 81 * 256) * 4)
__global__ void __launch_bounds__(512, 2)
k_gates(const float* __restrict__ X,
        const float* __restrict__ Wl,
        const float* __restrict__ s0) {
    extern __shared__ float sm[];
    float* Xst = sm;              // [k][t] transposed, pitch 34 (32 t rows)
    float* Ws  = sm + WS_OFF;     // [k][c64][gate]  (one m-half)
    int b = blockIdx.x >> 1, th = blockIdx.x & 1;
    int t0 = th * 32;
    int tid = threadIdx.x;
    int wid = tid >> 5, lane = tid & 31;
    int wrow = (wid & 7) * 4;     // 4 t-rows per warp (within the 32)
    int ml = wid >> 3;            // 32-col band within the 64-col half

    for (int idx = tid; idx < 32 * 81; idx += 512) {
        int t = idx / 81, k = idx - t * 81;
        Xst[k * XST_PITCH + t] = X[(b * T_ + t0 + t) * N_ + k];
    }

    for (int stage = 0; stage < 2; stage++) {
        __syncthreads();
        for (int idx = tid; idx < 81 * 256; idx += 512) {
            int k = idx >> 8, j = idx & 255;
            int g = j >> 6, c = j & 63;          // source-coalesced in c
            Ws[k * 256 + c * 4 + g] = Wl[k * G4_ + g * M_ + stage * 64 + c];
        }
        __syncthreads();

        ull acc[4][2];
#pragma unroll
        for (int g = 0; g < 4; g++)
#pragma unroll
            for (int p = 0; p < 2; p++) acc[g][p] = 0ull;

#pragma unroll 3
        for (int k = 0; k < 81; k++) {
            const float* xr = &Xst[k * XST_PITCH + wrow];
            ull x0 = *(const ull*)(xr + 0);
            ull x1 = *(const ull*)(xr + 2);
            float4 w4 = *(const float4*)&Ws[k * 256 + (ml * 32 + lane) * 4];
            ull di = pk2(w4.x, w4.x);
            ull df = pk2(w4.y, w4.y);
            ull dg = pk2(w4.z, w4.z);
            ull do_ = pk2(w4.w, w4.w);
            acc[0][0] = fma2(x0, di, acc[0][0]);
            acc[0][1] = fma2(x1, di, acc[0][1]);
            acc[1][0] = fma2(x0, df, acc[1][0]);
            acc[1][1] = fma2(x1, df, acc[1][1]);
            acc[2][0] = fma2(x0, dg, acc[2][0]);
            acc[2][1] = fma2(x1, dg, acc[2][1]);
            acc[3][0] = fma2(x0, do_, acc[3][0]);
            acc[3][1] = fma2(x1, do_, acc[3][1]);
        }

        int m = stage * 64 + ml * 32 + lane;
        float zi = g_z[b * G4_ + 0 * M_ + m];
        float zf = g_z[b * G4_ + 1 * M_ + m];
        float zg = g_z[b * G4_ + 2 * M_ + m];
        float zo = g_z[b * G4_ + 3 * M_ + m];
        float sv = s0[b * M_ + m];
#pragma unroll
        for (int p = 0; p < 2; p++) {
            float vi[2], vf[2], vg[2], vo[2];
            unpk2(acc[0][p], vi[0], vi[1]);
            unpk2(acc[1][p], vf[0], vf[1]);
            unpk2(acc[2][p], vg[0], vg[1]);
            unpk2(acc[3][p], vo[0], vo[1]);
#pragma unroll
            for (int h = 0; h < 2; h++) {
                int t = t0 + wrow + 2 * p + h;
                float iv = sigm(vi[h] + zi);
                float fv = sigm(vf[h] + zf);
                float gv = tanhe(vg[h] + zg);
                float ov = sigm(vo[h] + zo);
                float cc = fv * sv + iv * gv;
                float hh = ov * tanhe(cc);
                g_hc[(b * T_ + t) * 256 + m]       = hh;
                g_hc[(b * T_ + t) * 256 + M_ + m]  = cc;
            }
        }
    }
}

// ---------------------------------------------------------------------------
// K2 (fully fused): per b —
//   phase1: A[t,j] = hc[t,:] @ We_w[:,j] + We_b[j]       (64x64, K=256)
//   phase2: U[i,k] = sum_t X[b,t,i]*Ue_w[t,k] + Ue_b[k]  (81x64); X kept in smem
//   phase3: per warp per t: scores -> softmax (registers) -> alpha LUT (smem)
//           -> stream out[t,b,:,:] = Xs * alphaLUT  (STG.128, streaming hint)
// grid = B, 512 threads. No g_alpha, no k_out.
// SC region sized for its biggest user: phase1 scratch = 4160+4096 = 8256 floats.
// ---------------------------------------------------------------------------
#define AS_OFF  0
#define US_OFF  (64 * 65)                       // 4160
#define XS_OFF  (US_OFF + 96 * 65)              // 10400 (pad rows: lane+64 safe)
#define SC_OFF  (XS_OFF + 5184)                 // 15584; 15584*4%16==0 ✓
#define SC_SZ   (64 * 65 + 64 * 64)             // 8256 (phase1 max user)
#define LUT_OFF SC_OFF                          // phase3: 16 warps * 81 float4 = 5184
#define AL_OFF  (SC_OFF + 16 * 81 * 4)          // 20768 .. 22064 (within SC) ✓
#define VS_OFF  (SC_OFF + SC_SZ)                // 23840
#define UB_OFF  (VS_OFF + 64)                   // 23904
#define ATTN_SMEM ((UB_OFF + 64) * 4)           // 95872 B
__global__ void __launch_bounds__(512, 1)
k_attn(const float* __restrict__ Wew, const float* __restrict__ Web,
       const float* __restrict__ X,   const float* __restrict__ Uew,
       const float* __restrict__ Ueb, const float* __restrict__ vew,
       float* __restrict__ out) {
    extern __shared__ float sm[];
    float* As = sm + AS_OFF;    // [t][k] pitch 65
    float* Us = sm + US_OFF;    // [i][k] pitch 65 (rows padded to 96)
    float* Xs = sm + XS_OFF;    // X[b] flat 5184, live through phase3
    float* SC = sm + SC_OFF;    // phase1: hcs+Wes; phase2: Ues; phase3: LUT+AL
    float* vs = sm + VS_OFF;
    float* ub = sm + UB_OFF;
    int b = blockIdx.x, tid = threadIdx.x;

    // ---- phase 1: A = hc @ We_w + We_b ----
    {
        float* hcs = SC;            // 64*65
        float* Wes = SC + 64 * 65;  // 64*64
        int r0 = (tid >> 4) * 2;
        int c0 = (tid & 15) * 4;
        float acc[2][4];
#pragma unroll
        for (int i = 0; i < 2; i++)
#pragma unroll
            for (int j = 0; j < 4; j++) acc[i][j] = Web[c0 + j];

        for (int kc = 0; kc < 4; kc++) {
            __syncthreads();
            for (int idx = tid; idx < 4096; idx += 512) {
                int t = idx >> 6, kk = idx & 63;
                hcs[t * 65 + kk] = g_hc[(b * T_ + t) * 256 + kc * 64 + kk];
            }
            for (int idx = tid; idx < 4096; idx += 512)
                Wes[idx] = Wew[kc * 4096 + idx];
            __syncthreads();
#pragma unroll 4
            for (int k = 0; k < 64; k++) {
                float a0 = hcs[r0 * 65 + k];
                float a1 = hcs[(r0 + 1) * 65 + k];
                float4 w = *(const float4*)&Wes[k * 64 + c0];
                acc[0][0] += a0 * w.x; acc[0][1] += a0 * w.y;
                acc[0][2] += a0 * w.z; acc[0][3] += a0 * w.w;
                acc[1][0] += a1 * w.x; acc[1][1] += a1 * w.y;
                acc[1][2] += a1 * w.z; acc[1][3] += a1 * w.w;
            }
        }
#pragma unroll
        for (int i = 0; i < 2; i++)
#pragma unroll
            for (int j = 0; j < 4; j++)
                As[(r0 + i) * 65 + c0 + j] = acc[i][j];
    }

    // ---- phase 2: U (X stays in Xs for phase 3) ----
    __syncthreads();
    {
        float* Ues = SC;           // 4096 (overwrites phase1 scratch)
        for (int idx = tid; idx < 5184; idx += 512) Xs[idx] = X[b * 5184 + idx];
        for (int idx = tid; idx < 4096; idx += 512) Ues[idx] = Uew[idx];
        if (tid < 64)                vs[tid]       = vew[tid];
        else if (tid < 128)          ub[tid - 64]  = Ueb[tid - 64];
        __syncthreads();

        if (tid < 336) {
            int ig = tid >> 4, kq = tid & 15, i0 = ig * 4;
            int ni = (i0 + 4 <= N_) ? 4 : (N_ - i0);
            float4 bias = *(const float4*)&ub[kq * 4];
            float4 a0 = bias, a1 = bias, a2 = bias, a3 = bias;
#pragma unroll 4
            for (int t = 0; t < T_; t++) {
                float4 u = *(const float4*)&Ues[t * 64 + kq * 4];
                const float* xr = &Xs[t * N_ + i0];
                float x0 = xr[0], x1 = xr[1], x2 = xr[2], x3 = xr[3];
                a0.x += x0 * u.x; a0.y += x0 * u.y; a0.z += x0 * u.z; a0.w += x0 * u.w;
                a1.x += x1 * u.x; a1.y += x1 * u.y; a1.z += x1 * u.z; a1.w += x1 * u.w;
                a2.x += x2 * u.x; a2.y += x2 * u.y; a2.z += x2 * u.z; a2.w += x2 * u.w;
                a3.x += x3 * u.x; a3.y += x3 * u.y; a3.z += x3 * u.z; a3.w += x3 * u.w;
            }
            float4 av[4] = {a0, a1, a2, a3};
            for (int j = 0; j < ni; j++) {
                float* up = &Us[(i0 + j) * 65 + kq * 4];
                up[0] = av[j].x; up[1] = av[j].y; up[2] = av[j].z; up[3] = av[j].w;
            }
        }
    }

    // ---- phase 3: scores + softmax + fused output streaming ----
    __syncthreads();
    {
        int wid = tid >> 5, lane = tid & 31;
        bool v2 = (lane + 64 < N_);
        float*  alw  = sm + AL_OFF  + wid * 81;
        float4* lut  = (float4*)(sm + LUT_OFF) + wid * 81;
        const float4* X4s = (const float4*)Xs;

        for (int t = wid; t < T_; t += 16) {
            float a0 = 0.f, a1 = 0.f, a2 = 0.f;
            const float* Ap = &As[t * 65];
            const float* U0 = &Us[lane * 65];
            const float* U1 = &Us[(lane + 32) * 65];
            const float* U2 = &Us[(lane + 64) * 65];  // padded region: safe read
#pragma unroll 4
            for (int k = 0; k < 64; k++) {
                float av = Ap[k], vv = vs[k];
                a0 += vv * tanhap(av + U0[k]);
                a1 += vv * tanhap(av + U1[k]);
                a2 += vv * tanhap(av + U2[k]);
            }
            if (!v2) a2 = -1e30f;
            float mx = fmaxf(fmaxf(a0, a1), a2);
#pragma unroll
            for (int off = 16; off; off >>= 1)
                mx = fmaxf(mx, __shfl_xor_sync(0xffffffffu, mx, off));
            float e0 = __expf(a0 - mx);
            float e1 = __expf(a1 - mx);
            float e2 = __expf(a2 - mx);   // 0 when invalid (a2=-1e30)
            float sum = e0 + e1 + e2;
#pragma unroll
            for (int off = 16; off; off >>= 1)
                sum += __shfl_xor_sync(0xffffffffu, sum, off);
            float inv = frcp(sum);
            alw[lane]      = e0 * inv;
            alw[lane + 32] = e1 * inv;
            if (v2) alw[lane + 64] = e2 * inv;
            __syncwarp();

            // expanded float4 alpha LUT (period-81 mapping, gcd(4,81)=1)
#pragma unroll
            for (int rr = 0; rr < 3; rr++) {
                int r = lane + rr * 32;
                if (r < N_) {
                    int i0 = (4 * r) % N_;
                    int i1 = i0 + 1; if (i1 >= N_) i1 -= N_;
                    int i2 = i1 + 1; if (i2 >= N_) i2 -= N_;
                    int i3 = i2 + 1; if (i3 >= N_) i3 -= N_;
                    lut[r] = make_float4(alw[i0], alw[i1], alw[i2], alw[i3]);
                }
            }
            __syncwarp();

            // stream out[t,b,:,:] — 1296 float4s per t, warp-contiguous
            float4* O = (float4*)out + (size_t)(t * B_ + b) * 1296;
            int r = lane % N_;
#pragma unroll 4
            for (int j = lane; j < 1296; j += 32) {
                float4 x = X4s[j];
                float4 a = lut[r];
                float4 o = make_float4(x.x * a.x, x.y * a.y, x.z * a.z, x.w * a.w);
                __stcs(&O[j], o);
                r += 32; if (r >= N_) r -= N_;
            }
            __syncwarp();
        }
    }
}

// ---------------------------------------------------------------------------
extern "C" void kernel_launch(void* const* d_in, const int* in_sizes, int n_in,
                              void* d_out, int out_size) {
    const float* X   = (const float*)d_in[0];
    const float* h0  = (const float*)d_in[1];
    const float* s0  = (const float*)d_in[2];
    const float* Wl  = (const float*)d_in[3];
    const float* Ul  = (const float*)d_in[4];
    const float* bl  = (const float*)d_in[5];
    const float* Wew = (const float*)d_in[6];
    const float* Web = (const float*)d_in[7];
    const float* Uew = (const float*)d_in[8];
    const float* Ueb = (const float*)d_in[9];
    const float* vew = (const float*)d_in[10];
    // d_in[11] = ve_b: constant pre-softmax shift -> softmax-invariant, unused.
    float* out = (float*)d_out;

    cudaFuncSetAttribute(k_gates, cudaFuncAttributeMaxDynamicSharedMemorySize, GATES_SMEM);
    cudaFuncSetAttribute(k_attn,  cudaFuncAttributeMaxDynamicSharedMemorySize, ATTN_SMEM);

    k_z    <<<B_,     G4_>>>(h0, Ul, bl);
    k_gates<<<B_ * 2, 512, GATES_SMEM>>>(X, Wl, s0);
    k_attn <<<B_,     512, ATTN_SMEM>>>(Wew, Web, X, Uew, Ueb, vew, out);
    (void)in_sizes; (void)n_in; (void)out_size;
}